// round 5
// baseline (speedup 1.0000x reference)
#include <cuda_runtime.h>
#include <cuda_bf16.h>
#include <cstdint>

// PerspectiveNet768x2, int16 fixed-point, TMA-bulk + LDS pipeline.
//
// R3/R4: two different LDG kernels both pinned at ~70 B/cyc/SM = the LDG
// L1tex-wavefront ceiling, with L2 at only 77%. R5 bypasses L1tex: rows are
// staged L2->SMEM with cp.async.bulk (async proxy, no LDG wavefronts) and
// consumed via LDS (128 B/cyc/SM). Binding resource becomes L2 itself.
//
// Quantization unchanged: int16 scale 40940, 16-feature SIMD partials
// (max |partial| = 16*2047 = 32752 < 32767), exact int32 combine.

#define NACT        32
#define THREADS     256
#define NFEAT       3840
#define WPR         512u              // uint32 words per 1024-col row
#define ZROW        (2u * NFEAT)      // all-zero row (device arrays zero-init)
#define ROW_BYTES   2048
#define RPS         4                 // rows per stage
#define NSLOTS      4
#define NSTAGES     16                // 64 rows / RPS
#define STAGE_BYTES (RPS * ROW_BYTES) // 8192
#define QSCALE      40940.0f
#define QINV        (1.0f / 40940.0f)

// [white 0..3839 | black 3840..7679 | zero row 7680]
__device__ __align__(256) unsigned g_q[(2u * NFEAT + 1u) * WPR];

__global__ void convert_kernel(const float2* __restrict__ Ww,
                               const float2* __restrict__ Wb)
{
    const unsigned n = NFEAT * WPR;
    unsigned i = blockIdx.x * blockDim.x + threadIdx.x;
    if (i >= n) return;
    float2 a = __ldg(&Ww[i]);
    int q0 = __float2int_rn(a.x * QSCALE);
    int q1 = __float2int_rn(a.y * QSCALE);
    g_q[i] = ((unsigned)q0 & 0xFFFFu) | ((unsigned)q1 << 16);
    float2 c = __ldg(&Wb[i]);
    int p0 = __float2int_rn(c.x * QSCALE);
    int p1 = __float2int_rn(c.y * QSCALE);
    g_q[n + i] = ((unsigned)p0 & 0xFFFFu) | ((unsigned)p1 << 16);
}

__device__ __forceinline__ int lo16(unsigned w) { return (int)((short)(w & 0xFFFFu)); }
__device__ __forceinline__ int hi16(unsigned w) { return (int)((short)(w >> 16)); }

__device__ __forceinline__ uint32_t smem_u32(const void* p) {
    return (uint32_t)__cvta_generic_to_shared(p);
}

__device__ __forceinline__ void mbar_init(uint32_t a, uint32_t cnt) {
    asm volatile("mbarrier.init.shared.b64 [%0], %1;" :: "r"(a), "r"(cnt) : "memory");
}
__device__ __forceinline__ void mbar_expect_tx(uint32_t a, uint32_t bytes) {
    asm volatile("mbarrier.arrive.expect_tx.shared.b64 _, [%0], %1;"
                 :: "r"(a), "r"(bytes) : "memory");
}
__device__ __forceinline__ void bulk_g2s(uint32_t dst, const void* src, uint32_t mbar) {
    asm volatile("cp.async.bulk.shared::cluster.global.mbarrier::complete_tx::bytes "
                 "[%0], [%1], %2, [%3];"
                 :: "r"(dst), "l"(src), "n"(ROW_BYTES), "r"(mbar) : "memory");
}
__device__ __forceinline__ void mbar_wait(uint32_t mbar, uint32_t parity) {
    asm volatile(
        "{\n\t.reg .pred P;\n"
        "W_%=:\n\t"
        "mbarrier.try_wait.parity.acquire.cta.shared::cta.b64 P, [%0], %1;\n\t"
        "@P bra D_%=;\n\t"
        "bra W_%=;\n"
        "D_%=:\n\t}"
        :: "r"(mbar), "r"(parity) : "memory");
}
__device__ __forceinline__ void fence_async() {
    asm volatile("fence.proxy.async.shared::cta;" ::: "memory");
}

__global__ __launch_bounds__(THREADS)
void nnue_gather_kernel(
    const int*    __restrict__ fw,    // [B,32]
    const int*    __restrict__ fb,    // [B,32]
    const int*    __restrict__ stm,   // [B] int32
    const float4* __restrict__ bw,    // [256]  (1024 floats)
    const float4* __restrict__ bb,
    const float4* __restrict__ Wout,  // [512]  (2048 floats)
    const float*  __restrict__ bout,
    float*        __restrict__ out)   // [B]
{
    __shared__ __align__(128) unsigned char sbuf[NSLOTS][STAGE_BYTES]; // 32 KB
    __shared__ __align__(8)  unsigned long long smbar[NSLOTS];
    __shared__ unsigned sidx[2 * NACT];
    __shared__ float    sred[THREADS / 32];

    const int b   = blockIdx.x;
    const int tid = threadIdx.x;

    // Stage absolute row ids: -1 -> zero row; black offset by NFEAT.
    if (tid < NACT) {
        int v = fw[b * NACT + tid];
        sidx[tid] = (v < 0) ? ZROW : (unsigned)v;
    } else if (tid < 2 * NACT) {
        int v = fb[b * NACT + (tid - NACT)];
        sidx[tid] = (v < 0) ? ZROW : (unsigned)v + NFEAT;
    }

    if (tid == 0) {
        #pragma unroll
        for (int s = 0; s < NSLOTS; ++s) mbar_init(smem_u32(&smbar[s]), 1u);
        fence_async();
    }
    __syncthreads();

    const uint32_t buf0 = smem_u32(&sbuf[0][0]);
    const uint32_t mb0  = smem_u32(&smbar[0]);

    // Prime 3 stages.
    if (tid == 0) {
        #pragma unroll
        for (int s = 0; s < NSLOTS - 1; ++s) {
            const uint32_t mb = mb0 + (s & 3) * 8u;
            mbar_expect_tx(mb, STAGE_BYTES);
            #pragma unroll
            for (int j = 0; j < RPS; ++j)
                bulk_g2s(buf0 + (uint32_t)(s & 3) * STAGE_BYTES + j * ROW_BYTES,
                         (const char*)g_q + (size_t)sidx[s * RPS + j] * ROW_BYTES,
                         mb);
        }
    }

    // Four 16-feature SIMD partials: stages 0-3 -> pw0, 4-7 -> pw1,
    // 8-11 -> pb0, 12-15 -> pb1 (compile-time under full unroll).
    uint2 pw0 = make_uint2(0u, 0u), pw1 = make_uint2(0u, 0u);
    uint2 pb0 = make_uint2(0u, 0u), pb1 = make_uint2(0u, 0u);

    #pragma unroll
    for (int s = 0; s < NSTAGES; ++s) {
        const int slot = s & 3;
        mbar_wait(mb0 + slot * 8u, (s >> 2) & 1);

        const unsigned char* sp = &sbuf[slot][0] + tid * 8;
        uint2& acc = (s < 4) ? pw0 : (s < 8) ? pw1 : (s < 12) ? pb0 : pb1;
        #pragma unroll
        for (int j = 0; j < RPS; ++j) {
            uint2 v = *(const uint2*)(sp + j * ROW_BYTES);
            acc.x = __vadd2(acc.x, v.x);
            acc.y = __vadd2(acc.y, v.y);
        }
        __syncthreads();   // everyone done reading this slot

        if (tid == 0 && s + 3 < NSTAGES) {
            const int ns = s + 3;
            const uint32_t mb = mb0 + (ns & 3) * 8u;
            fence_async();   // order prior generic reads before async writes
            mbar_expect_tx(mb, STAGE_BYTES);
            #pragma unroll
            for (int j = 0; j < RPS; ++j)
                bulk_g2s(buf0 + (uint32_t)(ns & 3) * STAGE_BYTES + j * ROW_BYTES,
                         (const char*)g_q + (size_t)sidx[ns * RPS + j] * ROW_BYTES,
                         mb);
        }
    }

    // Epilogue: thread owns cols 4*tid .. 4*tid+3 of BOTH perspectives.
    const bool white = (__ldg(&stm[b]) != 0);
    const float4 bwv = bw[tid];
    const float4 bbv = bb[tid];
    const float4 w_w = Wout[(white ? 0 : 256) + tid];   // multiplies hidden_white
    const float4 w_b = Wout[(white ? 256 : 0) + tid];   // multiplies hidden_black

    #define ACTM(isum, bias, wc)                                        \
        ({ float _h = fmaf((float)(isum), QINV, (bias));                \
           _h = fminf(fmaxf(_h, 0.0f), 1.0f);                           \
           _h * _h * (wc); })

    float p = 0.0f;
    p += ACTM(lo16(pw0.x) + lo16(pw1.x), bwv.x, w_w.x);
    p += ACTM(hi16(pw0.x) + hi16(pw1.x), bwv.y, w_w.y);
    p += ACTM(lo16(pw0.y) + lo16(pw1.y), bwv.z, w_w.z);
    p += ACTM(hi16(pw0.y) + hi16(pw1.y), bwv.w, w_w.w);
    p += ACTM(lo16(pb0.x) + lo16(pb1.x), bbv.x, w_b.x);
    p += ACTM(hi16(pb0.x) + hi16(pb1.x), bbv.y, w_b.y);
    p += ACTM(lo16(pb0.y) + lo16(pb1.y), bbv.z, w_b.z);
    p += ACTM(hi16(pb0.y) + hi16(pb1.y), bbv.w, w_b.w);
    #undef ACTM

    #pragma unroll
    for (int o = 16; o > 0; o >>= 1)
        p += __shfl_down_sync(0xffffffffu, p, o);
    if ((tid & 31) == 0) sred[tid >> 5] = p;
    __syncthreads();

    if (tid == 0) {
        float s = 0.0f;
        #pragma unroll
        for (int k = 0; k < THREADS / 32; ++k) s += sred[k];
        out[b] = s + bout[0];
    }
}

extern "C" void kernel_launch(void* const* d_in, const int* in_sizes, int n_in,
                              void* d_out, int out_size)
{
    const int*    fw   = (const int*)d_in[0];
    const int*    fb   = (const int*)d_in[1];
    const int*    stm  = (const int*)d_in[2];
    const float2* Ww   = (const float2*)d_in[3];
    const float4* bw   = (const float4*)d_in[4];
    const float2* Wb   = (const float2*)d_in[5];
    const float4* bb   = (const float4*)d_in[6];
    const float4* Wout = (const float4*)d_in[7];
    const float*  bout = (const float*)d_in[8];
    float*        out  = (float*)d_out;

    const int B = in_sizes[0] / NACT;   // 16384

    const unsigned nwords = NFEAT * WPR;
    convert_kernel<<<(nwords + 255) / 256, 256>>>(Ww, Wb);
    nnue_gather_kernel<<<B, THREADS>>>(fw, fb, stm, bw, bb, Wout, bout, out);
}